// round 5
// baseline (speedup 1.0000x reference)
#include <cuda_runtime.h>
#include <cstdint>

// FraudDetectionHybrid — fused, dead-code-eliminated, mixed-pipe tanh:
//   layer 1: MUFU.TANH (scalar, unbounded args)
//   everything else: [7/6] rational tanh on packed f32x2 FMA pipe + scalar RCP
// Autoencoder is dead code. Sigmoids folded to 0.5+0.5*tanh(arg/2) with the
// affine folded into downstream weights.

static __device__ __forceinline__ float tanh_fast(float x) {
    float y;
    asm("tanh.approx.f32 %0, %1;" : "=f"(y) : "f"(x));
    return y;
}
static __device__ __forceinline__ float rcp_fast(float x) {
    float y;
    asm("rcp.approx.f32 %0, %1;" : "=f"(y) : "f"(x));
    return y;
}

// ---- packed f32x2 helpers ----
static __device__ __forceinline__ uint64_t pk(float lo, float hi) {
    uint64_t r;
    asm("mov.b64 %0, {%1, %2};" : "=l"(r) : "f"(lo), "f"(hi));
    return r;
}
static __device__ __forceinline__ void upk(float& lo, float& hi, uint64_t v) {
    asm("mov.b64 {%0, %1}, %2;" : "=f"(lo), "=f"(hi) : "l"(v));
}
static __device__ __forceinline__ uint64_t fma2(uint64_t a, uint64_t b, uint64_t c) {
    uint64_t d;
    asm("fma.rn.f32x2 %0, %1, %2, %3;" : "=l"(d) : "l"(a), "l"(b), "l"(c));
    return d;
}
static __device__ __forceinline__ uint64_t mul2(uint64_t a, uint64_t b) {
    uint64_t d;
    asm("mul.rn.f32x2 %0, %1, %2;" : "=l"(d) : "l"(a), "l"(b));
    return d;
}
static __device__ __forceinline__ uint64_t add2(uint64_t a, uint64_t b) {
    uint64_t d;
    asm("add.rn.f32x2 %0, %1, %2;" : "=l"(d) : "l"(a), "l"(b));
    return d;
}

// [7/6] continued-fraction rational tanh on a packed pair.
// tanh(x) ~ x*(10395 + 1260u + 21u^2) / (10395 + 4725u + 210u^2 + u^3), u=x^2
// err <= ~1e-5 for |x|<=2.5, <= 2.2e-4 for |x|<=4 — args here are bounded.
struct RatC {
    uint64_t c21, c1260, c10395, c210, c4725;
};
static __device__ __forceinline__ uint64_t tanh_rat2(uint64_t t, const RatC& rc) {
    const uint64_t u = mul2(t, t);
    uint64_t n = fma2(u, rc.c21, rc.c1260);
    n = fma2(u, n, rc.c10395);
    const uint64_t num = mul2(t, n);
    uint64_t h = add2(u, rc.c210);
    h = fma2(u, h, rc.c4725);
    h = fma2(u, h, rc.c10395);
    float dlo, dhi;
    upk(dlo, dhi, h);
    const uint64_t r = pk(rcp_fast(dlo), rcp_fast(dhi));
    return mul2(num, r);
}

constexpr int B_TOTAL  = 1048576;
constexpr int THREADS  = 256;
constexpr int BLOCKS   = 1024;
constexpr int NTHREADS = THREADS * BLOCKS;    // 262144 threads, 4 samples each

__global__ __launch_bounds__(THREADS)
void fraud_fused_kernel(const float4* __restrict__ x,
                        const float*  __restrict__ fW,   // [4,2,2]
                        const float*  __restrict__ fb,   // [4,2]
                        const float*  __restrict__ ck,   // [2,2]
                        const float*  __restrict__ w1,   // [4,2]
                        const float*  __restrict__ b1,   // [4]
                        const float*  __restrict__ w2,   // [2,4]
                        const float*  __restrict__ b2,   // [2]
                        float4*       __restrict__ out)
{
    RatC rc;
    rc.c21    = pk(21.0f, 21.0f);
    rc.c1260  = pk(1260.0f, 1260.0f);
    rc.c10395 = pk(10395.0f, 10395.0f);
    rc.c210   = pk(210.0f, 210.0f);
    rc.c4725  = pk(4725.0f, 4725.0f);

    // ---- layer-1 scalar coefs ----
    const float L1w00 = __ldg(&fW[0]), L1w01 = __ldg(&fW[1]);
    const float L1w10 = __ldg(&fW[2]), L1w11 = __ldg(&fW[3]);
    const float L1b0  = __ldg(&fb[0]), L1b1  = __ldg(&fb[1]);

    // ---- layers 2..4 packed coefs ----
    uint64_t W00[3], W01[3], W10[3], W11[3], B0[3], B1[3];
#pragma unroll
    for (int l = 0; l < 3; ++l) {
        const float a = __ldg(&fW[(l + 1) * 4 + 0]);
        const float b = __ldg(&fW[(l + 1) * 4 + 1]);
        const float c = __ldg(&fW[(l + 1) * 4 + 2]);
        const float d = __ldg(&fW[(l + 1) * 4 + 3]);
        const float e = __ldg(&fb[(l + 1) * 2 + 0]);
        const float f = __ldg(&fb[(l + 1) * 2 + 1]);
        W00[l] = pk(a, a); W01[l] = pk(b, b);
        W10[l] = pk(c, c); W11[l] = pk(d, d);
        B0[l]  = pk(e, e); B1[l]  = pk(f, f);
    }

    // conv: rows identical -> s = (k00+k10)h0 + (k01+k11)h1; sigmoid(s)=0.5+0.5*tanh(s/2)
    const float c0s = 0.5f * (__ldg(&ck[0]) + __ldg(&ck[2]));
    const float c1s = 0.5f * (__ldg(&ck[1]) + __ldg(&ck[3]));
    const uint64_t C0 = pk(c0s, c0s), C1 = pk(c1s, c1s);

    uint64_t W1a[4], W1bh[4], B1v[4];
#pragma unroll
    for (int j = 0; j < 4; ++j) {
        const float wa = __ldg(&w1[j * 2 + 0]);
        const float wb = __ldg(&w1[j * 2 + 1]);
        const float bb = __ldg(&b1[j]) + 0.5f * wb;  // absorbs the +0.5 sigmoid shift
        W1a[j]  = pk(wa, wa);
        W1bh[j] = pk(0.5f * wb, 0.5f * wb);
        B1v[j]  = pk(bb, bb);
    }

    uint64_t WD[4];
#pragma unroll
    for (int j = 0; j < 4; ++j) {
        const float wd = 0.5f * (__ldg(&w2[j]) - __ldg(&w2[4 + j]));
        WD[j] = pk(wd, wd);
    }
    const float bds = 0.5f * (__ldg(&b2[0]) - __ldg(&b2[1]));
    const uint64_t BD   = pk(bds, bds);
    const uint64_t HALF = pk(0.5f, 0.5f);

    const int tid = blockIdx.x * blockDim.x + threadIdx.x;

    const float4 va = __ldg(&x[tid]);
    const float4 vb = __ldg(&x[tid + NTHREADS]);

    // ---- layer 1: scalar MUFU.TANH on raw inputs (unbounded args) ----
    float s0[4] = {va.x, va.z, vb.x, vb.z};
    float s1[4] = {va.y, va.w, vb.y, vb.w};
    float l0[4], l1[4];
#pragma unroll
    for (int s = 0; s < 4; ++s) {
        l0[s] = tanh_fast(fmaf(L1w00, s0[s], fmaf(L1w01, s1[s], L1b0)));
        l1[s] = tanh_fast(fmaf(L1w10, s0[s], fmaf(L1w11, s1[s], L1b1)));
    }

    // ---- pack into 2 pairs, run the rest fully packed ----
    uint64_t A0[2] = {pk(l0[0], l0[1]), pk(l0[2], l0[3])};
    uint64_t A1[2] = {pk(l1[0], l1[1]), pk(l1[2], l1[3])};
    uint64_t P[2];

#pragma unroll
    for (int p = 0; p < 2; ++p) {
        uint64_t a0 = A0[p], a1 = A1[p];

        // fraud layers 2..4 (bounded args -> rational tanh)
#pragma unroll
        for (int l = 0; l < 3; ++l) {
            const uint64_t t0 = fma2(W00[l], a0, fma2(W01[l], a1, B0[l]));
            const uint64_t t1 = fma2(W10[l], a0, fma2(W11[l], a1, B1[l]));
            a0 = tanh_rat2(t0, rc);
            a1 = tanh_rat2(t1, rc);
        }

        // conv sigmoid (half-arg tanh)
        const uint64_t tc = tanh_rat2(fma2(C0, a0, mul2(C1, a1)), rc);

        // sampler hidden: 4 neurons
        uint64_t q0 = tanh_rat2(fma2(W1a[0], a0, fma2(W1bh[0], tc, B1v[0])), rc);
        uint64_t q1 = tanh_rat2(fma2(W1a[1], a0, fma2(W1bh[1], tc, B1v[1])), rc);
        uint64_t q2 = tanh_rat2(fma2(W1a[2], a0, fma2(W1bh[2], tc, B1v[2])), rc);
        uint64_t q3 = tanh_rat2(fma2(W1a[3], a0, fma2(W1bh[3], tc, B1v[3])), rc);

        // half logit-diff -> p0 = 0.5 + 0.5*tanh(d)
        uint64_t d = fma2(WD[0], q0, BD);
        d = fma2(WD[1], q1, d);
        d = fma2(WD[2], q2, d);
        d = fma2(WD[3], q3, d);
        P[p] = fma2(HALF, tanh_rat2(d, rc), HALF);
    }

    float pa, pb, pc, pd;
    upk(pa, pb, P[0]);
    upk(pc, pd, P[1]);
    out[tid]            = make_float4(pa, 1.0f - pa, pb, 1.0f - pb);
    out[tid + NTHREADS] = make_float4(pc, 1.0f - pc, pd, 1.0f - pd);
}

extern "C" void kernel_launch(void* const* d_in, const int* in_sizes, int n_in,
                              void* d_out, int out_size)
{
    // metadata order:
    // 0:x 1:fraud_W 2:fraud_b 3..14:enc/dec (dead) 15:conv_k 16:s_W1 17:s_b1 18:s_W2 19:s_b2
    const float4* x  = (const float4*)d_in[0];
    const float*  fW = (const float*)d_in[1];
    const float*  fb = (const float*)d_in[2];
    const float*  ck = (const float*)d_in[15];
    const float*  w1 = (const float*)d_in[16];
    const float*  b1 = (const float*)d_in[17];
    const float*  w2 = (const float*)d_in[18];
    const float*  b2 = (const float*)d_in[19];
    float4* out = (float4*)d_out;

    (void)in_sizes; (void)n_in; (void)out_size;

    fraud_fused_kernel<<<BLOCKS, THREADS>>>(x, fW, fb, ck, w1, b1, w2, b2, out);
}

// round 7
// speedup vs baseline: 1.1895x; 1.1895x over previous
#include <cuda_runtime.h>

// FraudDetectionHybrid — fused, dead-code-eliminated, dual-pipe tanh:
//   MUFU.TANH (XU pipe, rt16): layer-1 (unbounded args), conv, sampler hidden = 7/sample
//   [5/4] rational (FMA pipe + 1 RCP): fraud layers 2-4, final logit = 7/sample
// Rational is safe: R4 measured rel_err 1.35e-6 with rationals everywhere,
// proving all bounded-tanh args are ~<=2.2 where [5/4] err <= 5e-5.
// Autoencoder (enc_*/dec_*) is dead code and skipped.

static __device__ __forceinline__ float tanh_mufu(float x) {
    float y;
    asm("tanh.approx.f32 %0, %1;" : "=f"(y) : "f"(x));
    return y;
}
static __device__ __forceinline__ float rcp_fast(float x) {
    float y;
    asm("rcp.approx.f32 %0, %1;" : "=f"(y) : "f"(x));
    return y;
}
// [5/4] Pade/continued-fraction: tanh(t) ~ t*(945 + 105u + u^2)/(945 + 420u + 15u^2)
// 7 FMA-pipe ops + 1 RCP. err: 5e-5 @|t|<=2.2, 4e-4 @|t|<=3.
static __device__ __forceinline__ float tanh_rat(float t) {
    const float u = t * t;
    const float num = fmaf(u, u + 105.0f, 945.0f);
    const float den = fmaf(u, fmaf(u, 15.0f, 420.0f), 945.0f);
    return t * num * rcp_fast(den);
}

constexpr int B_TOTAL  = 1048576;
constexpr int THREADS  = 256;
constexpr int BLOCKS   = 1024;
constexpr int NTHREADS = THREADS * BLOCKS;    // 262144
constexpr int ITERS    = B_TOTAL / NTHREADS;  // 4 samples/thread -> 2 float4 iters

__global__ __launch_bounds__(THREADS)
void fraud_fused_kernel(const float4* __restrict__ x,
                        const float*  __restrict__ fW,   // [4,2,2]
                        const float*  __restrict__ fb,   // [4,2]
                        const float*  __restrict__ ck,   // [2,2]
                        const float*  __restrict__ w1,   // [4,2]
                        const float*  __restrict__ b1,   // [4]
                        const float*  __restrict__ w2,   // [2,4]
                        const float*  __restrict__ b2,   // [2]
                        float4*       __restrict__ out)
{
    // ---- coefficient setup (uniform per thread, L1-broadcast) ----
    float FW00[4], FW01[4], FW10[4], FW11[4], FB0[4], FB1[4];
#pragma unroll
    for (int l = 0; l < 4; ++l) {
        FW00[l] = __ldg(&fW[l * 4 + 0]);
        FW01[l] = __ldg(&fW[l * 4 + 1]);
        FW10[l] = __ldg(&fW[l * 4 + 2]);
        FW11[l] = __ldg(&fW[l * 4 + 3]);
        FB0[l]  = __ldg(&fb[l * 2 + 0]);
        FB1[l]  = __ldg(&fb[l * 2 + 1]);
    }

    // conv rows identical: s = (k00+k10)h0 + (k01+k11)h1
    // sigmoid(s) = 0.5 + 0.5*tanh(s/2); halves folded here, affine folded below.
    const float C0 = 0.5f * (__ldg(&ck[0]) + __ldg(&ck[2]));
    const float C1 = 0.5f * (__ldg(&ck[1]) + __ldg(&ck[3]));

    float W1a[4], W1bh[4], B1v[4];
#pragma unroll
    for (int j = 0; j < 4; ++j) {
        const float wa = __ldg(&w1[j * 2 + 0]);
        const float wb = __ldg(&w1[j * 2 + 1]);
        W1a[j]  = wa;
        W1bh[j] = 0.5f * wb;
        B1v[j]  = __ldg(&b1[j]) + 0.5f * wb;   // absorbs sigmoid's +0.5
    }

    // softmax(2) == sigmoid(l0-l1) = 0.5 + 0.5*tanh((l0-l1)/2)
    float WD[4];
#pragma unroll
    for (int j = 0; j < 4; ++j)
        WD[j] = 0.5f * (__ldg(&w2[j]) - __ldg(&w2[4 + j]));
    const float BD = 0.5f * (__ldg(&b2[0]) - __ldg(&b2[1]));

    const int tid = blockIdx.x * blockDim.x + threadIdx.x;

#pragma unroll
    for (int it = 0; it < ITERS / 2; ++it) {
        const int i = tid + it * NTHREADS;     // float4 index = 2 samples
        const float4 v = __ldg(&x[i]);

        float h0[2] = {v.x, v.z};
        float h1[2] = {v.y, v.w};
        float p0[2];

#pragma unroll
        for (int s = 0; s < 2; ++s) {
            // layer 1: MUFU (unbounded args)
            float a0 = tanh_mufu(fmaf(FW00[0], h0[s], fmaf(FW01[0], h1[s], FB0[0])));
            float a1 = tanh_mufu(fmaf(FW10[0], h0[s], fmaf(FW11[0], h1[s], FB1[0])));

            // layers 2..4: rational on FMA pipe (args bounded, err<=5e-5)
#pragma unroll
            for (int l = 1; l < 4; ++l) {
                const float t0 = fmaf(FW00[l], a0, fmaf(FW01[l], a1, FB0[l]));
                const float t1 = fmaf(FW10[l], a0, fmaf(FW11[l], a1, FB1[l]));
                a0 = tanh_rat(t0);
                a1 = tanh_rat(t1);
            }

            // conv sigmoid as half-arg tanh: MUFU
            const float tc = tanh_mufu(fmaf(C0, a0, C1 * a1));

            // sampler hidden: 4 neurons, MUFU
            const float q0 = tanh_mufu(fmaf(W1a[0], a0, fmaf(W1bh[0], tc, B1v[0])));
            const float q1 = tanh_mufu(fmaf(W1a[1], a0, fmaf(W1bh[1], tc, B1v[1])));
            const float q2 = tanh_mufu(fmaf(W1a[2], a0, fmaf(W1bh[2], tc, B1v[2])));
            const float q3 = tanh_mufu(fmaf(W1a[3], a0, fmaf(W1bh[3], tc, B1v[3])));

            // half logit-diff -> p0 = 0.5 + 0.5*tanh(d): rational
            float d = fmaf(WD[0], q0, BD);
            d = fmaf(WD[1], q1, d);
            d = fmaf(WD[2], q2, d);
            d = fmaf(WD[3], q3, d);
            p0[s] = fmaf(0.5f, tanh_rat(d), 0.5f);
        }

        out[i] = make_float4(p0[0], 1.0f - p0[0], p0[1], 1.0f - p0[1]);
    }
}

extern "C" void kernel_launch(void* const* d_in, const int* in_sizes, int n_in,
                              void* d_out, int out_size)
{
    // metadata order:
    // 0:x 1:fraud_W 2:fraud_b 3..14:enc/dec (dead) 15:conv_k 16:s_W1 17:s_b1 18:s_W2 19:s_b2
    const float4* x  = (const float4*)d_in[0];
    const float*  fW = (const float*)d_in[1];
    const float*  fb = (const float*)d_in[2];
    const float*  ck = (const float*)d_in[15];
    const float*  w1 = (const float*)d_in[16];
    const float*  b1 = (const float*)d_in[17];
    const float*  w2 = (const float*)d_in[18];
    const float*  b2 = (const float*)d_in[19];
    float4* out = (float4*)d_out;

    (void)in_sizes; (void)n_in; (void)out_size;

    fraud_fused_kernel<<<BLOCKS, THREADS>>>(x, fW, fb, ck, w1, b1, w2, b2, out);
}